// round 1
// baseline (speedup 1.0000x reference)
#include <cuda_runtime.h>
#include <cuda_bf16.h>

// Problem constants
#define BB 4
#define TT 1024
#define CC 768
#define NH 12
#define HD 64
#define BT (BB*TT)          // 4096
#define N_QKV (3*CC)        // 2304

// Scratch (allocation-free rule: __device__ globals)
__device__ float g_q[BB*NH*TT*HD];
__device__ float g_k[BB*NH*TT*HD];
__device__ float g_v[BB*NH*TT*HD];
__device__ float g_y[BT*CC];

// ---------------------------------------------------------------------------
// Kernel 1: qkv = x @ Wqkv + bqkv, scattered to head-major q/k/v
// M=4096, K=768, N=2304. Tile 128x128x8, 256 threads, 8x8 per thread.
// ---------------------------------------------------------------------------
__global__ __launch_bounds__(256) void qkv_gemm_kernel(
    const float* __restrict__ A,      // x [4096,768]
    const float* __restrict__ Bm,     // Wqkv [768,2304]
    const float* __restrict__ bias)   // [2304]
{
    __shared__ float As[8][132];
    __shared__ float Bs[8][132];

    const int tid = threadIdx.x;
    const int m0 = blockIdx.y * 128;
    const int n0 = blockIdx.x * 128;
    const int tx = tid & 15;
    const int ty = tid >> 4;

    const int arow = tid >> 1;
    const int acol = (tid & 1) * 4;
    const int brow = tid >> 5;
    const int bcol = (tid & 31) * 4;

    float acc[8][8];
    #pragma unroll
    for (int i = 0; i < 8; i++)
        #pragma unroll
        for (int j = 0; j < 8; j++) acc[i][j] = 0.f;

    for (int k0 = 0; k0 < CC; k0 += 8) {
        float4 av = *(const float4*)&A[(m0 + arow) * CC + k0 + acol];
        As[acol + 0][arow] = av.x;
        As[acol + 1][arow] = av.y;
        As[acol + 2][arow] = av.z;
        As[acol + 3][arow] = av.w;
        float4 bv = *(const float4*)&Bm[(k0 + brow) * N_QKV + n0 + bcol];
        *(float4*)&Bs[brow][bcol] = bv;
        __syncthreads();

        #pragma unroll
        for (int kk = 0; kk < 8; kk++) {
            float a[8], b[8];
            *(float4*)(a)     = *(const float4*)&As[kk][ty * 8];
            *(float4*)(a + 4) = *(const float4*)&As[kk][ty * 8 + 4];
            *(float4*)(b)     = *(const float4*)&Bs[kk][tx * 8];
            *(float4*)(b + 4) = *(const float4*)&Bs[kk][tx * 8 + 4];
            #pragma unroll
            for (int i = 0; i < 8; i++)
                #pragma unroll
                for (int j = 0; j < 8; j++)
                    acc[i][j] = fmaf(a[i], b[j], acc[i][j]);
        }
        __syncthreads();
    }

    // Epilogue: scatter into g_q/g_k/g_v laid out [B, NH, T, HD]
    // Within a 128-col block: "which" (q/k/v) is constant (768 % 128 == 0).
    // Within a thread's 8 cols: head is constant (cols are within one 8-aligned run).
    const int ncol0 = n0 + tx * 8;
    const int which = ncol0 / CC;
    const int c0 = ncol0 - which * CC;
    const int h = c0 >> 6;
    const int d0 = c0 & 63;
    float* dst = (which == 0) ? g_q : (which == 1) ? g_k : g_v;

    float bb_[8];
    #pragma unroll
    for (int j = 0; j < 8; j++) bb_[j] = bias[ncol0 + j];

    #pragma unroll
    for (int i = 0; i < 8; i++) {
        int m = m0 + ty * 8 + i;
        int b_ = m >> 10;          // /T
        int t_ = m & 1023;
        float* row = dst + (((b_ * NH + h) * TT) + t_) * HD + d0;
        float4 v0 = make_float4(acc[i][0] + bb_[0], acc[i][1] + bb_[1],
                                acc[i][2] + bb_[2], acc[i][3] + bb_[3]);
        float4 v1 = make_float4(acc[i][4] + bb_[4], acc[i][5] + bb_[5],
                                acc[i][6] + bb_[6], acc[i][7] + bb_[7]);
        *(float4*)(row)     = v0;
        *(float4*)(row + 4) = v1;
    }
}

// ---------------------------------------------------------------------------
// Kernel 2: flash attention (causal). One CTA = (64 q-rows, one head, one batch).
// 256 threads. Streams 64-key tiles with online softmax.
// ---------------------------------------------------------------------------
#define ALD 68   // padded row length for smem tiles

__global__ __launch_bounds__(256) void attn_kernel()
{
    extern __shared__ float sm[];
    float* Qt = sm;                  // [64][ALD], transposed: Qt[d][r]
    float* Kt = Qt + 64 * ALD;       // [64][ALD], transposed: Kt[d][c]
    float* Vs = Kt + 64 * ALD;       // [64][ALD], Vs[c][d]
    float* St = Vs + 64 * ALD;       // [64][ALD], transposed: St[c][r]
    float* mrow = St + 64 * ALD;     // [64]
    float* lrow = mrow + 64;         // [64]
    float* arow = lrow + 64;         // [64]

    const int tid = threadIdx.x;
    const int qt = blockIdx.x;       // q tile 0..15
    const int h  = blockIdx.y;
    const int b  = blockIdx.z;
    const int tx = tid & 15;
    const int ty = tid >> 4;

    const float* qb = g_q + (size_t)((b * NH + h) * TT) * HD;
    const float* kb = g_k + (size_t)((b * NH + h) * TT) * HD;
    const float* vb = g_v + (size_t)((b * NH + h) * TT) * HD;

    // Load Q tile, transposed
    #pragma unroll
    for (int s = 0; s < 4; s++) {
        int idx = tid + s * 256;
        int row = idx >> 4;
        int col4 = (idx & 15) * 4;
        float4 v = *(const float4*)&qb[(qt * 64 + row) * HD + col4];
        Qt[(col4 + 0) * ALD + row] = v.x;
        Qt[(col4 + 1) * ALD + row] = v.y;
        Qt[(col4 + 2) * ALD + row] = v.z;
        Qt[(col4 + 3) * ALD + row] = v.w;
    }
    if (tid < 64) { mrow[tid] = -1e30f; lrow[tid] = 0.f; }

    float o[4][4];
    #pragma unroll
    for (int i = 0; i < 4; i++)
        #pragma unroll
        for (int j = 0; j < 4; j++) o[i][j] = 0.f;

    __syncthreads();

    for (int j0 = 0; j0 <= qt; j0++) {
        // Load K (transposed) and V tiles
        #pragma unroll
        for (int s = 0; s < 4; s++) {
            int idx = tid + s * 256;
            int row = idx >> 4;
            int col4 = (idx & 15) * 4;
            float4 kv = *(const float4*)&kb[(j0 * 64 + row) * HD + col4];
            Kt[(col4 + 0) * ALD + row] = kv.x;
            Kt[(col4 + 1) * ALD + row] = kv.y;
            Kt[(col4 + 2) * ALD + row] = kv.z;
            Kt[(col4 + 3) * ALD + row] = kv.w;
            float4 vv = *(const float4*)&vb[(j0 * 64 + row) * HD + col4];
            *(float4*)&Vs[row * ALD + col4] = vv;
        }
        __syncthreads();

        // S = Q K^T  (4x4 per thread over a 64x64 tile)
        float acc[4][4];
        #pragma unroll
        for (int i = 0; i < 4; i++)
            #pragma unroll
            for (int j = 0; j < 4; j++) acc[i][j] = 0.f;

        #pragma unroll 8
        for (int d = 0; d < 64; d++) {
            float4 a = *(const float4*)&Qt[d * ALD + ty * 4];
            float4 bq = *(const float4*)&Kt[d * ALD + tx * 4];
            float av[4] = {a.x, a.y, a.z, a.w};
            float bv_[4] = {bq.x, bq.y, bq.z, bq.w};
            #pragma unroll
            for (int i = 0; i < 4; i++)
                #pragma unroll
                for (int j = 0; j < 4; j++)
                    acc[i][j] = fmaf(av[i], bv_[j], acc[i][j]);
        }

        // scale + causal mask; store transposed St[c][r]
        const bool diag = (j0 == qt);
        #pragma unroll
        for (int i = 0; i < 4; i++) {
            int r = ty * 4 + i;
            #pragma unroll
            for (int j = 0; j < 4; j++) {
                int c = tx * 4 + j;
                float s = acc[i][j] * 0.125f;
                if (diag && c > r) s = -1e30f;
                St[c * ALD + r] = s;
            }
        }
        __syncthreads();

        // Online softmax: one thread per q row
        if (tid < 64) {
            int r = tid;
            float mo = mrow[r];
            float mx = mo;
            #pragma unroll 8
            for (int c = 0; c < 64; c++) mx = fmaxf(mx, St[c * ALD + r]);
            float sum = 0.f;
            #pragma unroll 8
            for (int c = 0; c < 64; c++) {
                float p = __expf(St[c * ALD + r] - mx);
                St[c * ALD + r] = p;
                sum += p;
            }
            float al = __expf(mo - mx);
            arow[r] = al;
            mrow[r] = mx;
            lrow[r] = lrow[r] * al + sum;
        }
        __syncthreads();

        // O = O*alpha + P @ V
        float al[4];
        #pragma unroll
        for (int i = 0; i < 4; i++) al[i] = arow[ty * 4 + i];
        #pragma unroll
        for (int i = 0; i < 4; i++)
            #pragma unroll
            for (int j = 0; j < 4; j++) o[i][j] *= al[i];

        #pragma unroll 8
        for (int c = 0; c < 64; c++) {
            float4 a = *(const float4*)&St[c * ALD + ty * 4];
            float4 vv = *(const float4*)&Vs[c * ALD + tx * 4];
            float av[4] = {a.x, a.y, a.z, a.w};
            float bv_[4] = {vv.x, vv.y, vv.z, vv.w};
            #pragma unroll
            for (int i = 0; i < 4; i++)
                #pragma unroll
                for (int j = 0; j < 4; j++)
                    o[i][j] = fmaf(av[i], bv_[j], o[i][j]);
        }
        __syncthreads();   // protect Kt/Vs/St before next tile
    }

    // Epilogue: normalize and write to g_y [B, T, C] (head-interleaved)
    #pragma unroll
    for (int i = 0; i < 4; i++) {
        int r = ty * 4 + i;
        float inv = 1.f / lrow[r];
        float4 v = make_float4(o[i][0] * inv, o[i][1] * inv,
                               o[i][2] * inv, o[i][3] * inv);
        *(float4*)&g_y[(size_t)(b * TT + qt * 64 + r) * CC + h * HD + tx * 4] = v;
    }
}

#define ATTN_SMEM ((4 * 64 * ALD + 3 * 64) * sizeof(float))

// ---------------------------------------------------------------------------
// Kernel 3: out = y @ Wproj + bproj. M=4096, K=768, N=768. Same tiling.
// ---------------------------------------------------------------------------
__global__ __launch_bounds__(256) void proj_gemm_kernel(
    const float* __restrict__ Bm,     // Wproj [768,768]
    const float* __restrict__ bias,   // [768]
    float* __restrict__ out)          // [4096,768]
{
    __shared__ float As[8][132];
    __shared__ float Bs[8][132];

    const int tid = threadIdx.x;
    const int m0 = blockIdx.y * 128;
    const int n0 = blockIdx.x * 128;
    const int tx = tid & 15;
    const int ty = tid >> 4;

    const int arow = tid >> 1;
    const int acol = (tid & 1) * 4;
    const int brow = tid >> 5;
    const int bcol = (tid & 31) * 4;

    float acc[8][8];
    #pragma unroll
    for (int i = 0; i < 8; i++)
        #pragma unroll
        for (int j = 0; j < 8; j++) acc[i][j] = 0.f;

    for (int k0 = 0; k0 < CC; k0 += 8) {
        float4 av = *(const float4*)&g_y[(size_t)(m0 + arow) * CC + k0 + acol];
        As[acol + 0][arow] = av.x;
        As[acol + 1][arow] = av.y;
        As[acol + 2][arow] = av.z;
        As[acol + 3][arow] = av.w;
        float4 bv = *(const float4*)&Bm[(k0 + brow) * CC + n0 + bcol];
        *(float4*)&Bs[brow][bcol] = bv;
        __syncthreads();

        #pragma unroll
        for (int kk = 0; kk < 8; kk++) {
            float a[8], b[8];
            *(float4*)(a)     = *(const float4*)&As[kk][ty * 8];
            *(float4*)(a + 4) = *(const float4*)&As[kk][ty * 8 + 4];
            *(float4*)(b)     = *(const float4*)&Bs[kk][tx * 8];
            *(float4*)(b + 4) = *(const float4*)&Bs[kk][tx * 8 + 4];
            #pragma unroll
            for (int i = 0; i < 8; i++)
                #pragma unroll
                for (int j = 0; j < 8; j++)
                    acc[i][j] = fmaf(a[i], b[j], acc[i][j]);
        }
        __syncthreads();
    }

    float bb_[8];
    #pragma unroll
    for (int j = 0; j < 8; j++) bb_[j] = bias[n0 + tx * 8 + j];

    #pragma unroll
    for (int i = 0; i < 8; i++) {
        int m = m0 + ty * 8 + i;
        float* row = out + (size_t)m * CC + n0 + tx * 8;
        float4 v0 = make_float4(acc[i][0] + bb_[0], acc[i][1] + bb_[1],
                                acc[i][2] + bb_[2], acc[i][3] + bb_[3]);
        float4 v1 = make_float4(acc[i][4] + bb_[4], acc[i][5] + bb_[5],
                                acc[i][6] + bb_[6], acc[i][7] + bb_[7]);
        *(float4*)(row)     = v0;
        *(float4*)(row + 4) = v1;
    }
}

// ---------------------------------------------------------------------------
extern "C" void kernel_launch(void* const* d_in, const int* in_sizes, int n_in,
                              void* d_out, int out_size)
{
    const float* x     = (const float*)d_in[0];
    const float* Wqkv  = (const float*)d_in[1];
    const float* bqkv  = (const float*)d_in[2];
    const float* Wproj = (const float*)d_in[3];
    const float* bproj = (const float*)d_in[4];
    float* out = (float*)d_out;

    cudaFuncSetAttribute(attn_kernel,
                         cudaFuncAttributeMaxDynamicSharedMemorySize,
                         (int)ATTN_SMEM);

    qkv_gemm_kernel<<<dim3(N_QKV / 128, BT / 128), 256>>>(x, Wqkv, bqkv);
    attn_kernel<<<dim3(TT / 64, NH, BB), 256, ATTN_SMEM>>>();
    proj_gemm_kernel<<<dim3(CC / 128, BT / 128), 256>>>(Wproj, bproj, out);
}

// round 3
// speedup vs baseline: 2.2497x; 2.2497x over previous
#include <cuda_runtime.h>
#include <cuda_bf16.h>

// Problem constants
#define BB 4
#define TT 1024
#define CC 768
#define NH 12
#define HD 64
#define BT (BB*TT)          // 4096
#define N_QKV (3*CC)        // 2304

// Scratch (allocation-free rule: __device__ globals)
__device__ float g_q[BB*NH*TT*HD];
__device__ float g_k[BB*NH*TT*HD];
__device__ float g_v[BB*NH*TT*HD];
__device__ float g_y[BT*CC];

// ---------------------------------------------------------------------------
// Helpers: tf32 convert + m16n8k8 tf32 MMA
// ---------------------------------------------------------------------------
__device__ __forceinline__ unsigned f2tf32(float f) {
    unsigned r;
    asm("cvt.rna.tf32.f32 %0, %1;" : "=r"(r) : "f"(f));
    return r;
}

__device__ __forceinline__ void mma8(float* c, const unsigned* a, const unsigned* b) {
    asm volatile(
        "mma.sync.aligned.m16n8k8.row.col.f32.tf32.tf32.f32 "
        "{%0,%1,%2,%3}, {%4,%5,%6,%7}, {%8,%9}, {%0,%1,%2,%3};"
        : "+f"(c[0]), "+f"(c[1]), "+f"(c[2]), "+f"(c[3])
        : "r"(a[0]), "r"(a[1]), "r"(a[2]), "r"(a[3]),
          "r"(b[0]), "r"(b[1]));
}

// ---------------------------------------------------------------------------
// GEMM mainloop (tf32 mma): C[128x128] tile, 256 threads / 8 warps.
// Warp grid 2(m) x 4(n); warp tile 64x32; per warp: 4 m-tiles x 4 n-tiles.
// As[m][20] (bank-perm: 20g+t distinct), Bs[k][136] (8t+g distinct).
// ---------------------------------------------------------------------------
#define GA_LD 20
#define GB_LD 136

template<int N_GLOBAL>
__device__ __forceinline__ void gemm_mainloop(
    const float* __restrict__ A, const float* __restrict__ Bm,
    int m0, int n0, unsigned* As, unsigned* Bs, float acc[4][4][4])
{
    const int tid  = threadIdx.x;
    const int warp = tid >> 5;
    const int lane = tid & 31;
    const int g = lane >> 2, t = lane & 3;
    const int wm = warp >> 2;   // 0..1
    const int wn = warp & 3;    // 0..3

    for (int k0 = 0; k0 < CC; k0 += 16) {
        #pragma unroll
        for (int s = 0; s < 2; s++) {
            int idx = tid + s * 256;
            // A tile: 128 rows x 16 k  -> 512 float4
            int ar = idx >> 2, akq = idx & 3;
            float4 av = *(const float4*)&A[(size_t)(m0 + ar) * CC + k0 + akq * 4];
            uint4 ap = make_uint4(f2tf32(av.x), f2tf32(av.y), f2tf32(av.z), f2tf32(av.w));
            *(uint4*)&As[ar * GA_LD + akq * 4] = ap;
            // B tile: 16 k x 128 n -> 512 float4
            int bk = idx >> 5, bnq = idx & 31;
            float4 bv = *(const float4*)&Bm[(size_t)(k0 + bk) * N_GLOBAL + n0 + bnq * 4];
            uint4 bp = make_uint4(f2tf32(bv.x), f2tf32(bv.y), f2tf32(bv.z), f2tf32(bv.w));
            *(uint4*)&Bs[bk * GB_LD + bnq * 4] = bp;
        }
        __syncthreads();

        #pragma unroll
        for (int ks = 0; ks < 2; ks++) {
            const int kk = ks * 8;
            unsigned af[4][4], bf[4][2];
            #pragma unroll
            for (int mt = 0; mt < 4; mt++) {
                int r = wm * 64 + mt * 16 + g;
                af[mt][0] = As[r * GA_LD + kk + t];
                af[mt][1] = As[(r + 8) * GA_LD + kk + t];
                af[mt][2] = As[r * GA_LD + kk + t + 4];
                af[mt][3] = As[(r + 8) * GA_LD + kk + t + 4];
            }
            #pragma unroll
            for (int nt = 0; nt < 4; nt++) {
                int c = wn * 32 + nt * 8 + g;
                bf[nt][0] = Bs[(kk + t) * GB_LD + c];
                bf[nt][1] = Bs[(kk + t + 4) * GB_LD + c];
            }
            #pragma unroll
            for (int mt = 0; mt < 4; mt++)
                #pragma unroll
                for (int nt = 0; nt < 4; nt++)
                    mma8(acc[mt][nt], af[mt], bf[nt]);
        }
        __syncthreads();
    }
}

// ---------------------------------------------------------------------------
// Kernel 1: qkv = x @ Wqkv + bqkv, scattered head-major into g_q/g_k/g_v
// ---------------------------------------------------------------------------
__global__ __launch_bounds__(256) void qkv_gemm_kernel(
    const float* __restrict__ A,
    const float* __restrict__ Bm,
    const float* __restrict__ bias)
{
    __shared__ unsigned As[128 * GA_LD];
    __shared__ unsigned Bs[16 * GB_LD];

    const int tid  = threadIdx.x;
    const int warp = tid >> 5;
    const int lane = tid & 31;
    const int g = lane >> 2, t = lane & 3;
    const int wm = warp >> 2;
    const int wn = warp & 3;
    const int m0 = blockIdx.y * 128;
    const int n0 = blockIdx.x * 128;

    float acc[4][4][4];
    #pragma unroll
    for (int i = 0; i < 4; i++)
        #pragma unroll
        for (int j = 0; j < 4; j++)
            #pragma unroll
            for (int e = 0; e < 4; e++) acc[i][j][e] = 0.f;

    gemm_mainloop<N_QKV>(A, Bm, m0, n0, As, Bs, acc);

    // Epilogue: block's 128 cols lie fully inside one of q/k/v (768 % 128 == 0)
    const int which = n0 / CC;
    float* dst = (which == 0) ? g_q : (which == 1) ? g_k : g_v;

    #pragma unroll
    for (int mt = 0; mt < 4; mt++) {
        int r0 = m0 + wm * 64 + mt * 16 + g;
        #pragma unroll
        for (int nt = 0; nt < 4; nt++) {
            int cg = n0 + wn * 32 + nt * 8 + t * 2;
            int c0 = cg - which * CC;
            int h = c0 >> 6, d = c0 & 63;
            float b0v = bias[cg], b1v = bias[cg + 1];
            int b_ = r0 >> 10, t_ = r0 & 1023;
            float2 v0 = make_float2(acc[mt][nt][0] + b0v, acc[mt][nt][1] + b1v);
            *(float2*)&dst[(size_t)(((b_ * NH + h) * TT) + t_) * HD + d] = v0;
            int r1 = r0 + 8;
            b_ = r1 >> 10; t_ = r1 & 1023;
            float2 v1 = make_float2(acc[mt][nt][2] + b0v, acc[mt][nt][3] + b1v);
            *(float2*)&dst[(size_t)(((b_ * NH + h) * TT) + t_) * HD + d] = v1;
        }
    }
}

// ---------------------------------------------------------------------------
// Kernel 3: out = y @ Wproj + bproj
// ---------------------------------------------------------------------------
__global__ __launch_bounds__(256) void proj_gemm_kernel(
    const float* __restrict__ Bm,
    const float* __restrict__ bias,
    float* __restrict__ out)
{
    __shared__ unsigned As[128 * GA_LD];
    __shared__ unsigned Bs[16 * GB_LD];

    const int tid  = threadIdx.x;
    const int warp = tid >> 5;
    const int lane = tid & 31;
    const int g = lane >> 2, t = lane & 3;
    const int wm = warp >> 2;
    const int wn = warp & 3;
    const int m0 = blockIdx.y * 128;
    const int n0 = blockIdx.x * 128;

    float acc[4][4][4];
    #pragma unroll
    for (int i = 0; i < 4; i++)
        #pragma unroll
        for (int j = 0; j < 4; j++)
            #pragma unroll
            for (int e = 0; e < 4; e++) acc[i][j][e] = 0.f;

    gemm_mainloop<CC>(g_y, Bm, m0, n0, As, Bs, acc);

    #pragma unroll
    for (int mt = 0; mt < 4; mt++) {
        int r0 = m0 + wm * 64 + mt * 16 + g;
        #pragma unroll
        for (int nt = 0; nt < 4; nt++) {
            int cg = n0 + wn * 32 + nt * 8 + t * 2;
            float b0v = bias[cg], b1v = bias[cg + 1];
            float2 v0 = make_float2(acc[mt][nt][0] + b0v, acc[mt][nt][1] + b1v);
            *(float2*)&out[(size_t)r0 * CC + cg] = v0;
            float2 v1 = make_float2(acc[mt][nt][2] + b0v, acc[mt][nt][3] + b1v);
            *(float2*)&out[(size_t)(r0 + 8) * CC + cg] = v1;
        }
    }
}

// ---------------------------------------------------------------------------
// Kernel 2: causal flash attention with tf32 mma.
// CTA = (64 q rows, head, batch), 256 threads / 8 warps.
// Warp grid for both S and PV: 4(m) x 2(n); warp tile 16 x 32.
// ---------------------------------------------------------------------------
#define QS_LD 68   // bank: 4g+t distinct
#define PS_LD 68
#define KT_LD 72   // bank: 8t+g distinct
#define VS_LD 72

#define ATTN_SMEM ((2*64*QS_LD + 2*64*KT_LD + 192) * 4)

__global__ __launch_bounds__(256) void attn_kernel()
{
    extern __shared__ unsigned smu[];
    unsigned* Qs = smu;                       // [64][QS_LD] tf32 (pre-scaled)
    unsigned* Ps = Qs + 64 * QS_LD;           // [64][PS_LD] f32 then tf32
    unsigned* Kt = Ps + 64 * PS_LD;           // [64 d][KT_LD keys] tf32
    unsigned* Vs = Kt + 64 * KT_LD;           // [64 keys][VS_LD d] tf32
    float* mrow = (float*)(Vs + 64 * VS_LD);  // [64]
    float* lrow = mrow + 64;
    float* arow = lrow + 64;
    float* Psf = (float*)Ps;

    const int tid  = threadIdx.x;
    const int warp = tid >> 5;
    const int lane = tid & 31;
    const int g = lane >> 2, t = lane & 3;
    const int wm = warp >> 1;   // 0..3 (rows)
    const int wn = warp & 1;    // 0..1 (cols)
    const int rm = wm * 16;

    const int qt = gridDim.x - 1 - blockIdx.x;   // heavy tiles first
    const int h  = blockIdx.y;
    const int b  = blockIdx.z;

    const float* qb = g_q + (size_t)((b * NH + h) * TT) * HD;
    const float* kb = g_k + (size_t)((b * NH + h) * TT) * HD;
    const float* vb = g_v + (size_t)((b * NH + h) * TT) * HD;

    // Load Q tile (scale by 1/8 folded in; exact power of 2)
    #pragma unroll
    for (int s = 0; s < 4; s++) {
        int idx = tid + s * 256;            // 1024 float4s
        int row = idx >> 4, cq = (idx & 15) * 4;
        float4 qv = *(const float4*)&qb[(size_t)(qt * 64 + row) * HD + cq];
        Qs[row * QS_LD + cq + 0] = f2tf32(qv.x * 0.125f);
        Qs[row * QS_LD + cq + 1] = f2tf32(qv.y * 0.125f);
        Qs[row * QS_LD + cq + 2] = f2tf32(qv.z * 0.125f);
        Qs[row * QS_LD + cq + 3] = f2tf32(qv.w * 0.125f);
    }
    if (tid < 64) { mrow[tid] = -1e30f; lrow[tid] = 0.f; }

    float o[4][4];
    #pragma unroll
    for (int i = 0; i < 4; i++)
        #pragma unroll
        for (int e = 0; e < 4; e++) o[i][e] = 0.f;

    __syncthreads();

    for (int j0 = 0; j0 <= qt; j0++) {
        // ---- load K (transposed) and V tiles as tf32 ----
        #pragma unroll
        for (int s = 0; s < 4; s++) {
            int idx = tid + s * 256;
            int row = idx >> 4, cq = (idx & 15) * 4;
            float4 kv = *(const float4*)&kb[(size_t)(j0 * 64 + row) * HD + cq];
            Kt[(cq + 0) * KT_LD + row] = f2tf32(kv.x);
            Kt[(cq + 1) * KT_LD + row] = f2tf32(kv.y);
            Kt[(cq + 2) * KT_LD + row] = f2tf32(kv.z);
            Kt[(cq + 3) * KT_LD + row] = f2tf32(kv.w);
            float4 vv = *(const float4*)&vb[(size_t)(j0 * 64 + row) * HD + cq];
            uint4 vp = make_uint4(f2tf32(vv.x), f2tf32(vv.y), f2tf32(vv.z), f2tf32(vv.w));
            *(uint4*)&Vs[row * VS_LD + cq] = vp;
        }
        __syncthreads();

        // ---- S = Q K^T (pre-scaled) ----
        float sacc[4][4];
        #pragma unroll
        for (int nt = 0; nt < 4; nt++)
            #pragma unroll
            for (int e = 0; e < 4; e++) sacc[nt][e] = 0.f;

        #pragma unroll
        for (int ks = 0; ks < 8; ks++) {
            const int kk = ks * 8;
            unsigned af[4], bf[4][2];
            int r = rm + g;
            af[0] = Qs[r * QS_LD + kk + t];
            af[1] = Qs[(r + 8) * QS_LD + kk + t];
            af[2] = Qs[r * QS_LD + kk + t + 4];
            af[3] = Qs[(r + 8) * QS_LD + kk + t + 4];
            #pragma unroll
            for (int nt = 0; nt < 4; nt++) {
                int c = wn * 32 + nt * 8 + g;
                bf[nt][0] = Kt[(kk + t) * KT_LD + c];
                bf[nt][1] = Kt[(kk + t + 4) * KT_LD + c];
            }
            #pragma unroll
            for (int nt = 0; nt < 4; nt++)
                mma8(sacc[nt], af, bf[nt]);
        }

        // ---- write S to smem (mask on diagonal tile) ----
        const bool diag = (j0 == qt);
        #pragma unroll
        for (int nt = 0; nt < 4; nt++) {
            int col = wn * 32 + nt * 8 + t * 2;
            int r0 = rm + g;
            float s0 = sacc[nt][0], s1 = sacc[nt][1];
            float s2 = sacc[nt][2], s3 = sacc[nt][3];
            if (diag) {
                if (col     > r0) s0 = -1e30f;
                if (col + 1 > r0) s1 = -1e30f;
                if (col     > r0 + 8) s2 = -1e30f;
                if (col + 1 > r0 + 8) s3 = -1e30f;
            }
            *(float2*)&Psf[r0 * PS_LD + col] = make_float2(s0, s1);
            *(float2*)&Psf[(r0 + 8) * PS_LD + col] = make_float2(s2, s3);
        }
        __syncthreads();

        // ---- online softmax: 4 threads per row, 16 cols each ----
        {
            int row = tid >> 2, part = tid & 3;
            float v[16];
            #pragma unroll
            for (int q = 0; q < 4; q++) {
                float4 pv = *(const float4*)&Psf[row * PS_LD + part * 16 + q * 4];
                v[q*4+0] = pv.x; v[q*4+1] = pv.y; v[q*4+2] = pv.z; v[q*4+3] = pv.w;
            }
            float mx = v[0];
            #pragma unroll
            for (int i = 1; i < 16; i++) mx = fmaxf(mx, v[i]);
            mx = fmaxf(mx, __shfl_xor_sync(0xffffffffu, mx, 1));
            mx = fmaxf(mx, __shfl_xor_sync(0xffffffffu, mx, 2));
            float mo = mrow[row];
            float mn = fmaxf(mo, mx);
            float sum = 0.f;
            #pragma unroll
            for (int i = 0; i < 16; i++) {
                float p = __expf(v[i] - mn);
                v[i] = p;
                sum += p;
            }
            #pragma unroll
            for (int q = 0; q < 4; q++) {
                uint4 pp = make_uint4(f2tf32(v[q*4+0]), f2tf32(v[q*4+1]),
                                      f2tf32(v[q*4+2]), f2tf32(v[q*4+3]));
                *(uint4*)&Ps[row * PS_LD + part * 16 + q * 4] = pp;
            }
            sum += __shfl_xor_sync(0xffffffffu, sum, 1);
            sum += __shfl_xor_sync(0xffffffffu, sum, 2);
            if (part == 0) {
                float al = __expf(mo - mn);
                arow[row] = al;
                mrow[row] = mn;
                lrow[row] = lrow[row] * al + sum;
            }
        }
        __syncthreads();

        // ---- O = O*alpha + P @ V ----
        float al0 = arow[rm + g], al1 = arow[rm + g + 8];
        #pragma unroll
        for (int nt = 0; nt < 4; nt++) {
            o[nt][0] *= al0; o[nt][1] *= al0;
            o[nt][2] *= al1; o[nt][3] *= al1;
        }
        #pragma unroll
        for (int ks = 0; ks < 8; ks++) {
            const int kk = ks * 8;
            unsigned af[4], bf[4][2];
            int r = rm + g;
            af[0] = Ps[r * PS_LD + kk + t];
            af[1] = Ps[(r + 8) * PS_LD + kk + t];
            af[2] = Ps[r * PS_LD + kk + t + 4];
            af[3] = Ps[(r + 8) * PS_LD + kk + t + 4];
            #pragma unroll
            for (int nt = 0; nt < 4; nt++) {
                int c = wn * 32 + nt * 8 + g;
                bf[nt][0] = Vs[(kk + t) * VS_LD + c];
                bf[nt][1] = Vs[(kk + t + 4) * VS_LD + c];
            }
            #pragma unroll
            for (int nt = 0; nt < 4; nt++)
                mma8(o[nt], af, bf[nt]);
        }
        __syncthreads();   // protect Kt/Vs/Ps before next tile
    }

    // ---- epilogue: normalize, write to g_y [B, T, C] ----
    float inv0 = 1.f / lrow[rm + g];
    float inv1 = 1.f / lrow[rm + g + 8];
    #pragma unroll
    for (int nt = 0; nt < 4; nt++) {
        int col = h * HD + wn * 32 + nt * 8 + t * 2;
        int r0 = qt * 64 + rm + g;
        *(float2*)&g_y[(size_t)(b * TT + r0) * CC + col] =
            make_float2(o[nt][0] * inv0, o[nt][1] * inv0);
        *(float2*)&g_y[(size_t)(b * TT + r0 + 8) * CC + col] =
            make_float2(o[nt][2] * inv1, o[nt][3] * inv1);
    }
}

// ---------------------------------------------------------------------------
extern "C" void kernel_launch(void* const* d_in, const int* in_sizes, int n_in,
                              void* d_out, int out_size)
{
    const float* x     = (const float*)d_in[0];
    const float* Wqkv  = (const float*)d_in[1];
    const float* bqkv  = (const float*)d_in[2];
    const float* Wproj = (const float*)d_in[3];
    const float* bproj = (const float*)d_in[4];
    float* out = (float*)d_out;

    cudaFuncSetAttribute(attn_kernel,
                         cudaFuncAttributeMaxDynamicSharedMemorySize,
                         ATTN_SMEM);

    qkv_gemm_kernel<<<dim3(N_QKV / 128, BT / 128), 256>>>(x, Wqkv, bqkv);
    attn_kernel<<<dim3(TT / 64, NH, BB), 256, ATTN_SMEM>>>();
    proj_gemm_kernel<<<dim3(CC / 128, BT / 128), 256>>>(Wproj, bproj, out);
}

// round 6
// speedup vs baseline: 3.0870x; 1.3722x over previous
#include <cuda_runtime.h>
#include <cuda_bf16.h>

// Problem constants
#define BB 4
#define TT 1024
#define CC 768
#define NH 12
#define HD 64
#define BT (BB*TT)          // 4096
#define N_QKV (3*CC)        // 2304

// Scratch (allocation-free rule: __device__ globals).
// tf32 bit patterns stored in float arrays. 256-byte aligned: cp.async.cg
// needs 16B-aligned global addresses and the language only guarantees 4B.
__device__ __align__(256) float g_q[BB*NH*TT*HD];
__device__ __align__(256) float g_k[BB*NH*TT*HD];
__device__ __align__(256) float g_v[BB*NH*TT*HD];
__device__ __align__(256) float g_y[BT*CC];
__device__ __align__(256) float g_xa[BT*CC];
__device__ __align__(256) float g_wqkva[CC*N_QKV];
__device__ __align__(256) float g_wproja[CC*CC];

// ---------------------------------------------------------------------------
// Helpers
// ---------------------------------------------------------------------------
__device__ __forceinline__ unsigned f2tf32(float f) {
    unsigned r;
    asm("cvt.rna.tf32.f32 %0, %1;" : "=r"(r) : "f"(f));
    return r;
}

__device__ __forceinline__ void mma8(float* c, const unsigned* a, const unsigned* b) {
    asm volatile(
        "mma.sync.aligned.m16n8k8.row.col.f32.tf32.tf32.f32 "
        "{%0,%1,%2,%3}, {%4,%5,%6,%7}, {%8,%9}, {%0,%1,%2,%3};"
        : "+f"(c[0]), "+f"(c[1]), "+f"(c[2]), "+f"(c[3])
        : "r"(a[0]), "r"(a[1]), "r"(a[2]), "r"(a[3]),
          "r"(b[0]), "r"(b[1]));
}

__device__ __forceinline__ unsigned smem_u32(const void* p) {
    return (unsigned)__cvta_generic_to_shared(p);
}

#define CPA(dst, src) asm volatile("cp.async.cg.shared.global [%0], [%1], 16;" :: "r"(dst), "l"(src))
#define CPC()  asm volatile("cp.async.commit_group;")
#define CPW0() asm volatile("cp.async.wait_group 0;")
#define CPW1() asm volatile("cp.async.wait_group 1;")

// ---------------------------------------------------------------------------
// Elementwise fp32 -> tf32 (rna) pre-conversion
// ---------------------------------------------------------------------------
__global__ void cvt_kernel(const float* __restrict__ s, float* __restrict__ d, int n4)
{
    int i = blockIdx.x * blockDim.x + threadIdx.x;
    if (i < n4) {
        float4 v = ((const float4*)s)[i];
        uint4 o = make_uint4(f2tf32(v.x), f2tf32(v.y), f2tf32(v.z), f2tf32(v.w));
        ((uint4*)d)[i] = o;
    }
}

// ---------------------------------------------------------------------------
// GEMM mainloop: cp.async double-buffered, operands pre-converted tf32.
// C tile 128x128, 256 threads / 8 warps (2m x 4n), k-chunk 16.
// ---------------------------------------------------------------------------
#define GA_LD 20
#define GB_LD 136

template<int N_GLOBAL>
__device__ __forceinline__ void gemm_mainloop_ca(
    const float* __restrict__ A, const float* __restrict__ Bm,
    int m0, int n0, unsigned* As, unsigned* Bs, float acc[4][4][4])
{
    const int tid  = threadIdx.x;
    const int warp = tid >> 5;
    const int lane = tid & 31;
    const int g = lane >> 2, t = lane & 3;
    const int wm = warp >> 2;
    const int wn = warp & 3;

    const unsigned aBase = smem_u32(As);
    const unsigned bBase = smem_u32(Bs);

    int aoff[2], boff[2];
    size_t asrc[2], bsrc[2];
    #pragma unroll
    for (int s = 0; s < 2; s++) {
        int idx = tid + s * 256;
        int ar = idx >> 2, ak = (idx & 3) * 4;
        aoff[s] = ar * GA_LD + ak;
        asrc[s] = (size_t)(m0 + ar) * CC + ak;
        int bk = idx >> 5, bn = (idx & 31) * 4;
        boff[s] = bk * GB_LD + bn;
        bsrc[s] = (size_t)bk * N_GLOBAL + n0 + bn;
    }

#define GEMM_ISSUE(k0, buf) do {                                                     \
        CPA(aBase + ((buf)*128*GA_LD + aoff[0])*4u, A + asrc[0] + (k0));             \
        CPA(bBase + ((buf)*16*GB_LD  + boff[0])*4u, Bm + bsrc[0] + (size_t)(k0)*N_GLOBAL); \
        CPA(aBase + ((buf)*128*GA_LD + aoff[1])*4u, A + asrc[1] + (k0));             \
        CPA(bBase + ((buf)*16*GB_LD  + boff[1])*4u, Bm + bsrc[1] + (size_t)(k0)*N_GLOBAL); \
    } while (0)

    GEMM_ISSUE(0, 0);
    CPC();

    const int NIT = CC / 16;
    for (int it = 0; it < NIT; it++) {
        const int cur = it & 1;
        if (it + 1 < NIT) {
            GEMM_ISSUE((it + 1) * 16, cur ^ 1);
            CPC();
            CPW1();
        } else {
            CPW0();
        }
        __syncthreads();

        const unsigned* Ac = As + cur * 128 * GA_LD;
        const unsigned* Bc = Bs + cur * 16 * GB_LD;

        #pragma unroll
        for (int ks = 0; ks < 2; ks++) {
            const int kk = ks * 8;
            unsigned af[4][4], bf[4][2];
            #pragma unroll
            for (int mt = 0; mt < 4; mt++) {
                int r = wm * 64 + mt * 16 + g;
                af[mt][0] = Ac[r * GA_LD + kk + t];
                af[mt][1] = Ac[(r + 8) * GA_LD + kk + t];
                af[mt][2] = Ac[r * GA_LD + kk + t + 4];
                af[mt][3] = Ac[(r + 8) * GA_LD + kk + t + 4];
            }
            #pragma unroll
            for (int nt = 0; nt < 4; nt++) {
                int c = wn * 32 + nt * 8 + g;
                bf[nt][0] = Bc[(kk + t) * GB_LD + c];
                bf[nt][1] = Bc[(kk + t + 4) * GB_LD + c];
            }
            #pragma unroll
            for (int mt = 0; mt < 4; mt++)
                #pragma unroll
                for (int nt = 0; nt < 4; nt++)
                    mma8(acc[mt][nt], af[mt], bf[nt]);
        }
        __syncthreads();
    }
#undef GEMM_ISSUE
}

// ---------------------------------------------------------------------------
// Kernel 1: qkv = x @ Wqkv + bqkv -> head-major q/k/v (stored as tf32 bits;
// softmax scale 1/8 folded into q)
// ---------------------------------------------------------------------------
__global__ __launch_bounds__(256) void qkv_gemm_kernel(
    const float* __restrict__ A,
    const float* __restrict__ Bm,
    const float* __restrict__ bias)
{
    __shared__ unsigned As[2 * 128 * GA_LD];
    __shared__ unsigned Bs[2 * 16 * GB_LD];

    const int tid  = threadIdx.x;
    const int warp = tid >> 5;
    const int lane = tid & 31;
    const int g = lane >> 2, t = lane & 3;
    const int wm = warp >> 2;
    const int wn = warp & 3;
    const int m0 = blockIdx.y * 128;
    const int n0 = blockIdx.x * 128;

    float acc[4][4][4];
    #pragma unroll
    for (int i = 0; i < 4; i++)
        #pragma unroll
        for (int j = 0; j < 4; j++)
            #pragma unroll
            for (int e = 0; e < 4; e++) acc[i][j][e] = 0.f;

    gemm_mainloop_ca<N_QKV>(A, Bm, m0, n0, As, Bs, acc);

    const int which = n0 / CC;
    float* dst = (which == 0) ? g_q : (which == 1) ? g_k : g_v;
    const float sc = (which == 0) ? 0.125f : 1.0f;

    #pragma unroll
    for (int mt = 0; mt < 4; mt++) {
        int r0 = m0 + wm * 64 + mt * 16 + g;
        #pragma unroll
        for (int nt = 0; nt < 4; nt++) {
            int cg = n0 + wn * 32 + nt * 8 + t * 2;
            int c0 = cg - which * CC;
            int h = c0 >> 6, d = c0 & 63;
            float b0v = bias[cg], b1v = bias[cg + 1];
            int b_ = r0 >> 10, t_ = r0 & 1023;
            *(uint2*)&dst[(size_t)(((b_ * NH + h) * TT) + t_) * HD + d] =
                make_uint2(f2tf32((acc[mt][nt][0] + b0v) * sc),
                           f2tf32((acc[mt][nt][1] + b1v) * sc));
            int r1 = r0 + 8;
            b_ = r1 >> 10; t_ = r1 & 1023;
            *(uint2*)&dst[(size_t)(((b_ * NH + h) * TT) + t_) * HD + d] =
                make_uint2(f2tf32((acc[mt][nt][2] + b0v) * sc),
                           f2tf32((acc[mt][nt][3] + b1v) * sc));
        }
    }
}

// ---------------------------------------------------------------------------
// Kernel 3: out = y @ Wproj + bproj (fp32 output)
// ---------------------------------------------------------------------------
__global__ __launch_bounds__(256) void proj_gemm_kernel(
    const float* __restrict__ Bm,
    const float* __restrict__ bias,
    float* __restrict__ out)
{
    __shared__ unsigned As[2 * 128 * GA_LD];
    __shared__ unsigned Bs[2 * 16 * GB_LD];

    const int tid  = threadIdx.x;
    const int warp = tid >> 5;
    const int lane = tid & 31;
    const int g = lane >> 2, t = lane & 3;
    const int wm = warp >> 2;
    const int wn = warp & 3;
    const int m0 = blockIdx.y * 128;
    const int n0 = blockIdx.x * 128;

    float acc[4][4][4];
    #pragma unroll
    for (int i = 0; i < 4; i++)
        #pragma unroll
        for (int j = 0; j < 4; j++)
            #pragma unroll
            for (int e = 0; e < 4; e++) acc[i][j][e] = 0.f;

    gemm_mainloop_ca<CC>(g_y, Bm, m0, n0, As, Bs, acc);

    #pragma unroll
    for (int mt = 0; mt < 4; mt++) {
        int r0 = m0 + wm * 64 + mt * 16 + g;
        #pragma unroll
        for (int nt = 0; nt < 4; nt++) {
            int cg = n0 + wn * 32 + nt * 8 + t * 2;
            float b0v = bias[cg], b1v = bias[cg + 1];
            *(float2*)&out[(size_t)r0 * CC + cg] =
                make_float2(acc[mt][nt][0] + b0v, acc[mt][nt][1] + b1v);
            *(float2*)&out[(size_t)(r0 + 8) * CC + cg] =
                make_float2(acc[mt][nt][2] + b0v, acc[mt][nt][3] + b1v);
        }
    }
}

// ---------------------------------------------------------------------------
// Kernel 2: causal flash attention.
// CTA = (64 q rows, head, batch), 256 threads / 8 warps (4m x 2n).
// K/V double-buffered via cp.async; softmax in registers + small smem exchange.
// ---------------------------------------------------------------------------
#define QS_LD 68
#define PS_LD 68
#define KS_LD 68
#define VS_LD 72

#define ATTN_SMEM ((64*QS_LD + 64*PS_LD + 2*64*KS_LD + 2*64*VS_LD + 64 + 64 + 128 + 128) * 4)

__global__ __launch_bounds__(256) void attn_kernel()
{
    extern __shared__ unsigned smu[];
    unsigned* Qs = smu;                       // [64][QS_LD] tf32 (pre-scaled)
    unsigned* Ps = Qs + 64 * QS_LD;           // [64][PS_LD] tf32
    unsigned* Ks = Ps + 64 * PS_LD;           // 2 x [64 keys][KS_LD d] tf32
    unsigned* Vs = Ks + 2 * 64 * KS_LD;       // 2 x [64 keys][VS_LD d] tf32
    float* mrow = (float*)(Vs + 2 * 64 * VS_LD);  // [64]
    float* lrow = mrow + 64;                  // [64]
    float* pmax = lrow + 64;                  // [64][2]
    float* psum = pmax + 128;                 // [64][2]

    const int tid  = threadIdx.x;
    const int warp = tid >> 5;
    const int lane = tid & 31;
    const int g = lane >> 2, t = lane & 3;
    const int wm = warp >> 1;   // 0..3 (row stripe)
    const int wn = warp & 1;    // 0..1 (col half)
    const int rm = wm * 16;
    const int r0 = rm + g, r1 = rm + g + 8;

    const int qt = gridDim.x - 1 - blockIdx.x;   // heavy tiles first
    const int h  = blockIdx.y;
    const int b  = blockIdx.z;

    const float* qb = g_q + (size_t)((b * NH + h) * TT) * HD;
    const float* kb = g_k + (size_t)((b * NH + h) * TT) * HD;
    const float* vb = g_v + (size_t)((b * NH + h) * TT) * HD;

    const unsigned qB = smem_u32(Qs);
    const unsigned kB = smem_u32(Ks);
    const unsigned vB = smem_u32(Vs);

    int lrw[4], lcc[4];
    #pragma unroll
    for (int s = 0; s < 4; s++) {
        int idx = tid + s * 256;
        lrw[s] = idx >> 4;
        lcc[s] = (idx & 15) * 4;
    }

#define KV_ISSUE(j, buf) do {                                                          \
        _Pragma("unroll")                                                              \
        for (int s = 0; s < 4; s++) {                                                  \
            size_t so = (size_t)((j) * 64 + lrw[s]) * HD + lcc[s];                     \
            CPA(kB + ((buf)*64*KS_LD + lrw[s]*KS_LD + lcc[s])*4u, kb + so);            \
            CPA(vB + ((buf)*64*VS_LD + lrw[s]*VS_LD + lcc[s])*4u, vb + so);            \
        }                                                                              \
    } while (0)

    // Prologue: Q tile + first K/V tile in one async group
    #pragma unroll
    for (int s = 0; s < 4; s++)
        CPA(qB + (lrw[s]*QS_LD + lcc[s])*4u,
            qb + (size_t)(qt * 64 + lrw[s]) * HD + lcc[s]);
    KV_ISSUE(0, 0);
    CPC();

    if (tid < 64) { mrow[tid] = -1e30f; lrow[tid] = 0.f; }

    float o[4][4];
    #pragma unroll
    for (int i = 0; i < 4; i++)
        #pragma unroll
        for (int e = 0; e < 4; e++) o[i][e] = 0.f;

    for (int j0 = 0; j0 <= qt; j0++) {
        const int cur = j0 & 1;
        if (j0 < qt) {
            KV_ISSUE(j0 + 1, cur ^ 1);
            CPC();
            CPW1();
        } else {
            CPW0();
        }
        __syncthreads();

        const unsigned* Kc = Ks + cur * 64 * KS_LD;
        const unsigned* Vc = Vs + cur * 64 * VS_LD;

        // ---- S = Q K^T (scale pre-folded into Q) ----
        float sacc[4][4];
        #pragma unroll
        for (int nt = 0; nt < 4; nt++)
            #pragma unroll
            for (int e = 0; e < 4; e++) sacc[nt][e] = 0.f;

        #pragma unroll
        for (int ks = 0; ks < 8; ks++) {
            const int kk = ks * 8;
            unsigned af[4], bf[4][2];
            af[0] = Qs[r0 * QS_LD + kk + t];
            af[1] = Qs[r1 * QS_LD + kk + t];
            af[2] = Qs[r0 * QS_LD + kk + t + 4];
            af[3] = Qs[r1 * QS_LD + kk + t + 4];
            #pragma unroll
            for (int nt = 0; nt < 4; nt++) {
                int c = wn * 32 + nt * 8 + g;
                bf[nt][0] = Kc[c * KS_LD + kk + t];
                bf[nt][1] = Kc[c * KS_LD + kk + t + 4];
            }
            #pragma unroll
            for (int nt = 0; nt < 4; nt++)
                mma8(sacc[nt], af, bf[nt]);
        }

        // ---- causal mask on diagonal tile ----
        if (j0 == qt) {
            #pragma unroll
            for (int nt = 0; nt < 4; nt++) {
                int col = wn * 32 + nt * 8 + t * 2;
                if (col     > r0) sacc[nt][0] = -1e30f;
                if (col + 1 > r0) sacc[nt][1] = -1e30f;
                if (col     > r1) sacc[nt][2] = -1e30f;
                if (col + 1 > r1) sacc[nt][3] = -1e30f;
            }
        }

        // ---- register softmax: warp-partial max ----
        float tm0 = sacc[0][0], tm1 = sacc[0][2];
        #pragma unroll
        for (int nt = 0; nt < 4; nt++) {
            tm0 = fmaxf(tm0, fmaxf(sacc[nt][0], sacc[nt][1]));
            tm1 = fmaxf(tm1, fmaxf(sacc[nt][2], sacc[nt][3]));
        }
        tm0 = fmaxf(tm0, __shfl_xor_sync(0xffffffffu, tm0, 1));
        tm0 = fmaxf(tm0, __shfl_xor_sync(0xffffffffu, tm0, 2));
        tm1 = fmaxf(tm1, __shfl_xor_sync(0xffffffffu, tm1, 1));
        tm1 = fmaxf(tm1, __shfl_xor_sync(0xffffffffu, tm1, 2));
        if (t == 0) { pmax[r0 * 2 + wn] = tm0; pmax[r1 * 2 + wn] = tm1; }
        __syncthreads();

        const float mo0 = mrow[r0], mo1 = mrow[r1];
        const float mn0 = fmaxf(fmaxf(pmax[r0 * 2], pmax[r0 * 2 + 1]), mo0);
        const float mn1 = fmaxf(fmaxf(pmax[r1 * 2], pmax[r1 * 2 + 1]), mo1);
        const float al0 = __expf(mo0 - mn0);
        const float al1 = __expf(mo1 - mn1);

        float s0 = 0.f, s1 = 0.f;
        #pragma unroll
        for (int nt = 0; nt < 4; nt++) {
            float p00 = __expf(sacc[nt][0] - mn0);
            float p01 = __expf(sacc[nt][1] - mn0);
            float p10 = __expf(sacc[nt][2] - mn1);
            float p11 = __expf(sacc[nt][3] - mn1);
            s0 += p00 + p01;
            s1 += p10 + p11;
            int col = wn * 32 + nt * 8 + t * 2;
            *(uint2*)&Ps[r0 * PS_LD + col] = make_uint2(f2tf32(p00), f2tf32(p01));
            *(uint2*)&Ps[r1 * PS_LD + col] = make_uint2(f2tf32(p10), f2tf32(p11));
        }
        s0 += __shfl_xor_sync(0xffffffffu, s0, 1);
        s0 += __shfl_xor_sync(0xffffffffu, s0, 2);
        s1 += __shfl_xor_sync(0xffffffffu, s1, 1);
        s1 += __shfl_xor_sync(0xffffffffu, s1, 2);
        if (t == 0) { psum[r0 * 2 + wn] = s0; psum[r1 * 2 + wn] = s1; }

        // rescale O by alpha
        #pragma unroll
        for (int nt = 0; nt < 4; nt++) {
            o[nt][0] *= al0; o[nt][1] *= al0;
            o[nt][2] *= al1; o[nt][3] *= al1;
        }
        __syncthreads();

        // one thread per row: update running stats
        if (tid < 64) {
            int r = tid;
            float mo = mrow[r];
            float mn = fmaxf(fmaxf(pmax[r * 2], pmax[r * 2 + 1]), mo);
            float al = __expf(mo - mn);
            lrow[r] = lrow[r] * al + psum[r * 2] + psum[r * 2 + 1];
            mrow[r] = mn;
        }

        // ---- O += P @ V ----
        #pragma unroll
        for (int ks = 0; ks < 8; ks++) {
            const int kk = ks * 8;
            unsigned af[4], bf[4][2];
            af[0] = Ps[r0 * PS_LD + kk + t];
            af[1] = Ps[r1 * PS_LD + kk + t];
            af[2] = Ps[r0 * PS_LD + kk + t + 4];
            af[3] = Ps[r1 * PS_LD + kk + t + 4];
            #pragma unroll
            for (int nt = 0; nt < 4; nt++) {
                int c = wn * 32 + nt * 8 + g;
                bf[nt][0] = Vc[(kk + t) * VS_LD + c];
                bf[nt][1] = Vc[(kk + t + 4) * VS_LD + c];
            }
            #pragma unroll
            for (int nt = 0; nt < 4; nt++)
                mma8(o[nt], af, bf[nt]);
        }
        __syncthreads();   // protect Ks/Vs/Ps + stats before next tile
    }

    // ---- epilogue: normalize, store y as tf32 bits ----
    const float inv0 = 1.f / lrow[r0];
    const float inv1 = 1.f / lrow[r1];
    #pragma unroll
    for (int nt = 0; nt < 4; nt++) {
        int col = h * HD + wn * 32 + nt * 8 + t * 2;
        int rg = b * TT + qt * 64;
        *(uint2*)&g_y[(size_t)(rg + r0) * CC + col] =
            make_uint2(f2tf32(o[nt][0] * inv0), f2tf32(o[nt][1] * inv0));
        *(uint2*)&g_y[(size_t)(rg + r1) * CC + col] =
            make_uint2(f2tf32(o[nt][2] * inv1), f2tf32(o[nt][3] * inv1));
    }
#undef KV_ISSUE
}

// ---------------------------------------------------------------------------
extern "C" void kernel_launch(void* const* d_in, const int* in_sizes, int n_in,
                              void* d_out, int out_size)
{
    const float* x     = (const float*)d_in[0];
    const float* Wqkv  = (const float*)d_in[1];
    const float* bqkv  = (const float*)d_in[2];
    const float* Wproj = (const float*)d_in[3];
    const float* bproj = (const float*)d_in[4];
    float* out = (float*)d_out;

    cudaFuncSetAttribute(attn_kernel,
                         cudaFuncAttributeMaxDynamicSharedMemorySize,
                         ATTN_SMEM);

    float* xa; cudaGetSymbolAddress((void**)&xa, g_xa);
    float* wq; cudaGetSymbolAddress((void**)&wq, g_wqkva);
    float* wp; cudaGetSymbolAddress((void**)&wp, g_wproja);

    cvt_kernel<<<(BT*CC/4 + 255)/256, 256>>>(x, xa, BT*CC/4);
    cvt_kernel<<<(CC*N_QKV/4 + 255)/256, 256>>>(Wqkv, wq, CC*N_QKV/4);
    cvt_kernel<<<(CC*CC/4 + 255)/256, 256>>>(Wproj, wp, CC*CC/4);

    qkv_gemm_kernel<<<dim3(N_QKV / 128, BT / 128), 256>>>(xa, wq, bqkv);
    attn_kernel<<<dim3(TT / 64, NH, BB), 256, ATTN_SMEM>>>();
    proj_gemm_kernel<<<dim3(CC / 128, BT / 128), 256>>>(wp, bproj, out);
}